// round 1
// baseline (speedup 1.0000x reference)
#include <cuda_runtime.h>
#include <mma.h>
#include <math.h>

using namespace nvcuda;

#define HID    2304
#define HALF_D 1152
#define NHEADS 16
#define DH     144
#define SLEN   2048
#define MMAX   8192

// -------- scratch (static device globals; no runtime allocation) ----------
__device__ float g_q[(size_t)MMAX * HID];
__device__ float g_k[(size_t)MMAX * HID];
__device__ float g_v[(size_t)MMAX * HID];
__device__ float g_attn[(size_t)MMAX * HID];
__device__ float g_o[(size_t)MMAX * HID];
__device__ float g_cos[SLEN * HALF_D];
__device__ float g_sin[SLEN * HALF_D];

// ---------------------------------------------------------------------------
// RoPE table: cos/sin computed in double precision, stored f32.
// ---------------------------------------------------------------------------
__global__ void build_rope_kernel() {
    int idx = blockIdx.x * blockDim.x + threadIdx.x;
    if (idx >= SLEN * HALF_D) return;
    int pos = idx / HALF_D;
    int i   = idx - pos * HALF_D;
    double scale = (2.0 * (double)i) / (double)HID;
    double omega = exp(-scale * log(10000.0));
    double ang   = (double)pos * omega;
    g_cos[idx] = (float)cos(ang);
    g_sin[idx] = (float)sin(ang);
}

// ---------------------------------------------------------------------------
// C[M,N] = A[M,K] @ B[N,K]^T  via tf32 wmma. M%128==0, N%128==0, K%32==0.
// Block 256 threads = 8 warps (4x2), tile 128x128x32.
// ---------------------------------------------------------------------------
__global__ __launch_bounds__(256)
void gemm_tf32_kernel(const float* __restrict__ A, const float* __restrict__ B,
                      float* __restrict__ C, int M, int N, int K) {
    constexpr int BM = 128, BN = 128, BK = 32, LDS = 40;
    __shared__ float As[BM * LDS];
    __shared__ float Bs[BN * LDS];

    int bm  = blockIdx.y * BM;
    int bn  = blockIdx.x * BN;
    int tid = threadIdx.x;
    int warp = tid >> 5;
    int wm = (warp >> 1) * 32;  // warp row offset in tile (4 warps in M)
    int wn = (warp & 1) * 64;   // warp col offset in tile (2 warps in N)

    wmma::fragment<wmma::accumulator, 16, 16, 8, float> acc[2][4];
    #pragma unroll
    for (int i = 0; i < 2; i++)
        #pragma unroll
        for (int j = 0; j < 4; j++)
            wmma::fill_fragment(acc[i][j], 0.0f);

    for (int k0 = 0; k0 < K; k0 += BK) {
        // load 128x32 A tile and 128x32 B tile (each 1024 float4s, 4 per thread)
        #pragma unroll
        for (int i = 0; i < 4; i++) {
            int e = i * 256 + tid;
            int r = e >> 3;
            int c = (e & 7) * 4;
            float4 va = *(const float4*)(A + (size_t)(bm + r) * K + k0 + c);
            *(float4*)(As + r * LDS + c) = va;
            float4 vb = *(const float4*)(B + (size_t)(bn + r) * K + k0 + c);
            *(float4*)(Bs + r * LDS + c) = vb;
        }
        __syncthreads();

        #pragma unroll
        for (int kk = 0; kk < BK; kk += 8) {
            wmma::fragment<wmma::matrix_a, 16, 16, 8, wmma::precision::tf32, wmma::row_major> af[2];
            wmma::fragment<wmma::matrix_b, 16, 16, 8, wmma::precision::tf32, wmma::col_major> bf[4];
            #pragma unroll
            for (int i = 0; i < 2; i++) {
                wmma::load_matrix_sync(af[i], As + (wm + i * 16) * LDS + kk, LDS);
                #pragma unroll
                for (int e = 0; e < af[i].num_elements; e++)
                    af[i].x[e] = wmma::__float_to_tf32(af[i].x[e]);
            }
            #pragma unroll
            for (int j = 0; j < 4; j++) {
                wmma::load_matrix_sync(bf[j], Bs + (wn + j * 16) * LDS + kk, LDS);
                #pragma unroll
                for (int e = 0; e < bf[j].num_elements; e++)
                    bf[j].x[e] = wmma::__float_to_tf32(bf[j].x[e]);
            }
            #pragma unroll
            for (int i = 0; i < 2; i++)
                #pragma unroll
                for (int j = 0; j < 4; j++)
                    wmma::mma_sync(acc[i][j], af[i], bf[j], acc[i][j]);
        }
        __syncthreads();
    }

    #pragma unroll
    for (int i = 0; i < 2; i++)
        #pragma unroll
        for (int j = 0; j < 4; j++)
            wmma::store_matrix_sync(C + (size_t)(bm + wm + i * 16) * N + (bn + wn + j * 16),
                                    acc[i][j], N, wmma::mem_row_major);
}

// ---------------------------------------------------------------------------
// Bias add + RoPE on q,k (pairs over full hidden dim); bias add on v.
// ---------------------------------------------------------------------------
__global__ void rope_bias_kernel(const float* __restrict__ bq,
                                 const float* __restrict__ bk,
                                 const float* __restrict__ bv, int M) {
    int idx = blockIdx.x * blockDim.x + threadIdx.x;
    if (idx >= M * HALF_D) return;
    int row = idx / HALF_D;
    int i   = idx - row * HALF_D;
    int pos = row & (SLEN - 1);

    float c = g_cos[pos * HALF_D + i];
    float s = g_sin[pos * HALF_D + i];

    size_t base = (size_t)row * HID + 2 * i;
    float b0, b1;

    float2 qv = *(float2*)&g_q[base];
    b0 = bq[2 * i]; b1 = bq[2 * i + 1];
    qv.x += b0; qv.y += b1;
    float2 qr = make_float2(c * qv.x - s * qv.y, s * qv.x + c * qv.y);
    *(float2*)&g_q[base] = qr;

    float2 kv = *(float2*)&g_k[base];
    b0 = bk[2 * i]; b1 = bk[2 * i + 1];
    kv.x += b0; kv.y += b1;
    float2 kr = make_float2(c * kv.x - s * kv.y, s * kv.x + c * kv.y);
    *(float2*)&g_k[base] = kr;

    float2 vv = *(float2*)&g_v[base];
    vv.x += bv[2 * i]; vv.y += bv[2 * i + 1];
    *(float2*)&g_v[base] = vv;
}

// ---------------------------------------------------------------------------
// Head-mixing attention: per position p, 16x16 logits over heads, softmax,
// weighted sum of v. One block (256 threads) per position.
// q/k staged TRANSPOSED in smem ([j][n] stride 16) for conflict-free dots.
// ---------------------------------------------------------------------------
__global__ __launch_bounds__(256)
void attention_kernel(int M) {
    __shared__ float qt[DH * NHEADS];   // [j][n]
    __shared__ float kt[DH * NHEADS];   // [j][m]
    __shared__ float vs[HID];           // [m*DH + j]
    __shared__ float w[NHEADS * NHEADS];

    int p = blockIdx.x;
    int t = threadIdx.x;
    const float* qrow = g_q + (size_t)p * HID;
    const float* krow = g_k + (size_t)p * HID;
    const float* vrow = g_v + (size_t)p * HID;

    for (int c = t; c < HID; c += 256) {
        int n = c / DH;
        int j = c - n * DH;
        qt[j * NHEADS + n] = qrow[c];
        kt[j * NHEADS + n] = krow[c];
        vs[c] = vrow[c];
    }
    __syncthreads();

    // logits: thread (m = t>>4, n = t&15) -> conflict-free smem access
    {
        int m = t >> 4;
        int n = t & 15;
        float acc = 0.0f;
        #pragma unroll 8
        for (int j = 0; j < DH; j++)
            acc += qt[j * NHEADS + n] * kt[j * NHEADS + m];
        w[n * NHEADS + m] = acc * (1.0f / 12.0f);   // 1/sqrt(144)
    }
    __syncthreads();

    // softmax over m for each row n (threads 0..15)
    if (t < NHEADS) {
        float mx = -1e30f;
        #pragma unroll
        for (int m = 0; m < NHEADS; m++) mx = fmaxf(mx, w[t * NHEADS + m]);
        float sum = 0.0f;
        #pragma unroll
        for (int m = 0; m < NHEADS; m++) {
            float e = expf(w[t * NHEADS + m] - mx);
            w[t * NHEADS + m] = e;
            sum += e;
        }
        float inv = 1.0f / sum;
        #pragma unroll
        for (int m = 0; m < NHEADS; m++) w[t * NHEADS + m] *= inv;
    }
    __syncthreads();

    float* arow = g_attn + (size_t)p * HID;
    for (int c = t; c < HID; c += 256) {
        int n = c / DH;
        int j = c - n * DH;
        float acc = 0.0f;
        #pragma unroll
        for (int m = 0; m < NHEADS; m++)
            acc += w[n * NHEADS + m] * vs[m * DH + j];
        arow[c] = acc;
    }
}

// ---------------------------------------------------------------------------
// y = x + o + bo; out = LayerNorm(y) * g + b. One block per row.
// ---------------------------------------------------------------------------
__device__ __forceinline__ float block_sum(float v, float* red) {
    #pragma unroll
    for (int o = 16; o > 0; o >>= 1) v += __shfl_xor_sync(0xFFFFFFFFu, v, o);
    int warp = threadIdx.x >> 5, lane = threadIdx.x & 31;
    if (lane == 0) red[warp] = v;
    __syncthreads();
    if (warp == 0) {
        float x = (lane < 8) ? red[lane] : 0.0f;
        #pragma unroll
        for (int o = 4; o > 0; o >>= 1) x += __shfl_xor_sync(0xFFFFFFFFu, x, o);
        if (lane == 0) red[0] = x;
    }
    __syncthreads();
    float r = red[0];
    __syncthreads();
    return r;
}

__global__ __launch_bounds__(256)
void ln_kernel(const float* __restrict__ x, const float* __restrict__ bo,
               const float* __restrict__ gamma, const float* __restrict__ beta,
               float* __restrict__ out) {
    __shared__ float ybuf[HID];
    __shared__ float red[8];

    int row = blockIdx.x;
    int t = threadIdx.x;
    const float* xr = x + (size_t)row * HID;
    const float* orow = g_o + (size_t)row * HID;

    float s = 0.0f;
    for (int c = t; c < HID; c += 256) {
        float y = xr[c] + orow[c] + bo[c];
        ybuf[c] = y;
        s += y;
    }
    float total = block_sum(s, red);
    float mu = total * (1.0f / (float)HID);

    float vsum = 0.0f;
    for (int c = t; c < HID; c += 256) {
        float dy = ybuf[c] - mu;
        vsum += dy * dy;
    }
    float vtot = block_sum(vsum, red);
    float var = vtot * (1.0f / (float)HID);
    float rstd = rsqrtf(var + 1e-5f);

    float* orow_out = out + (size_t)row * HID;
    for (int c = t; c < HID; c += 256) {
        orow_out[c] = (ybuf[c] - mu) * rstd * gamma[c] + beta[c];
    }
}

// ---------------------------------------------------------------------------
extern "C" void kernel_launch(void* const* d_in, const int* in_sizes, int n_in,
                              void* d_out, int out_size) {
    const float* x  = (const float*)d_in[0];
    const float* wq = (const float*)d_in[1];
    const float* bq = (const float*)d_in[2];
    const float* wk = (const float*)d_in[3];
    const float* bk = (const float*)d_in[4];
    const float* wv = (const float*)d_in[5];
    const float* bv = (const float*)d_in[6];
    const float* wo = (const float*)d_in[7];
    const float* bo = (const float*)d_in[8];
    const float* g  = (const float*)d_in[9];
    const float* bl = (const float*)d_in[10];
    float* out = (float*)d_out;

    int M = in_sizes[0] / HID;   // b*s = 8192

    float *q, *k, *v, *attn, *o;
    cudaGetSymbolAddress((void**)&q,    g_q);
    cudaGetSymbolAddress((void**)&k,    g_k);
    cudaGetSymbolAddress((void**)&v,    g_v);
    cudaGetSymbolAddress((void**)&attn, g_attn);
    cudaGetSymbolAddress((void**)&o,    g_o);

    build_rope_kernel<<<(SLEN * HALF_D + 255) / 256, 256>>>();

    dim3 ggrid(HID / 128, M / 128);
    gemm_tf32_kernel<<<ggrid, 256>>>(x, wq, q, M, HID, HID);
    gemm_tf32_kernel<<<ggrid, 256>>>(x, wk, k, M, HID, HID);
    gemm_tf32_kernel<<<ggrid, 256>>>(x, wv, v, M, HID, HID);

    rope_bias_kernel<<<(M * HALF_D + 255) / 256, 256>>>(bq, bk, bv, M);

    attention_kernel<<<M, 256>>>(M);

    gemm_tf32_kernel<<<ggrid, 256>>>(attn, wo, o, M, HID, HID);

    ln_kernel<<<M, 256>>>(x, bo, g, bl, out);

    (void)n_in; (void)out_size;
}

// round 3
// speedup vs baseline: 1.6550x; 1.6550x over previous
#include <cuda_runtime.h>
#include <mma.h>
#include <math.h>
#include <cstdint>

using namespace nvcuda;

#define HID    2304
#define HALF_D 1152
#define NHEADS 16
#define DH     144
#define SLEN   2048
#define MMAX   8192

// -------- scratch (static device globals; no runtime allocation) ----------
__device__ float g_q[(size_t)MMAX * HID];
__device__ float g_k[(size_t)MMAX * HID];
__device__ float g_v[(size_t)MMAX * HID];
__device__ float g_attn[(size_t)MMAX * HID];
__device__ float g_o[(size_t)MMAX * HID];
__device__ float g_cos[SLEN * HALF_D];
__device__ float g_sin[SLEN * HALF_D];
__device__ double g_omega[HALF_D];

// ---------------------------------------------------------------------------
// RoPE tables. Omega in double (1152 threads), then cheap double angle
// reduction + float sincos (angle abs error < 1e-6 rad).
// ---------------------------------------------------------------------------
__global__ void build_omega_kernel() {
    int i = blockIdx.x * blockDim.x + threadIdx.x;
    if (i < HALF_D) {
        double scale = (2.0 * (double)i) / (double)HID;
        g_omega[i] = exp(-scale * log(10000.0));
    }
}

__global__ void build_rope_kernel() {
    int idx = blockIdx.x * blockDim.x + threadIdx.x;
    if (idx >= SLEN * HALF_D) return;
    int pos = idx / HALF_D;
    int i   = idx - pos * HALF_D;
    double ang = (double)pos * g_omega[i];
    double n = floor(ang * 0.15915494309189535);          // 1/(2*pi)
    double r = ang - n * 6.283185307179586476925286766559;
    float s, c;
    sincosf((float)r, &s, &c);
    g_cos[idx] = c;
    g_sin[idx] = s;
}

// ---------------------------------------------------------------------------
// cp.async helpers
// ---------------------------------------------------------------------------
__device__ __forceinline__ void cp_async16(uint32_t dst, const float* src) {
    asm volatile("cp.async.cg.shared.global [%0], [%1], 16;\n" :: "r"(dst), "l"(src));
}
__device__ __forceinline__ void cp_commit() {
    asm volatile("cp.async.commit_group;\n");
}
__device__ __forceinline__ void cp_wait1() {
    asm volatile("cp.async.wait_group 1;\n");
}

// ---------------------------------------------------------------------------
// C[M,N] = A[M,K] @ B[N,K]^T  via tf32 wmma.
// CTA tile 128x256x32, 3-stage cp.async pipeline, 8 warps (2x4), 64x64/warp.
// ---------------------------------------------------------------------------
#define BM 128
#define BN 256
#define BK 32
#define LDS_PAD 40
#define STAGE_FLOATS ((BM + BN) * LDS_PAD)   // 15360 floats = 61440 B
#define GEMM_SMEM_BYTES (3 * STAGE_FLOATS * 4)

__device__ __forceinline__ void load_stage(const float* __restrict__ A,
                                           const float* __restrict__ B,
                                           int K, int bm, int bn, int k0,
                                           float* As, float* Bs, int tid) {
    uint32_t sA = (uint32_t)__cvta_generic_to_shared(As);
    uint32_t sB = (uint32_t)__cvta_generic_to_shared(Bs);
    #pragma unroll
    for (int i = 0; i < 4; i++) {             // 128x32 A tile: 1024 float4
        int e = i * 256 + tid;
        int r = e >> 3;
        int c = (e & 7) * 4;
        cp_async16(sA + (uint32_t)(r * LDS_PAD + c) * 4,
                   A + (size_t)(bm + r) * K + k0 + c);
    }
    #pragma unroll
    for (int i = 0; i < 8; i++) {             // 256x32 B tile: 2048 float4
        int e = i * 256 + tid;
        int r = e >> 3;
        int c = (e & 7) * 4;
        cp_async16(sB + (uint32_t)(r * LDS_PAD + c) * 4,
                   B + (size_t)(bn + r) * K + k0 + c);
    }
}

__global__ __launch_bounds__(256, 1)
void gemm_tf32_kernel(const float* __restrict__ A, const float* __restrict__ B,
                      float* __restrict__ C, int M, int N, int K) {
    extern __shared__ float smem[];

    int bm  = blockIdx.y * BM;
    int bn  = blockIdx.x * BN;
    int tid = threadIdx.x;
    int warp = tid >> 5;
    int wm = (warp >> 2) * 64;   // 2 warps along M
    int wn = (warp & 3) * 64;    // 4 warps along N

    wmma::fragment<wmma::accumulator, 16, 16, 8, float> acc[4][4];
    #pragma unroll
    for (int i = 0; i < 4; i++)
        #pragma unroll
        for (int j = 0; j < 4; j++)
            wmma::fill_fragment(acc[i][j], 0.0f);

    int kIters = K / BK;   // 72

    // prologue: stages 0,1
    load_stage(A, B, K, bm, bn, 0, smem, smem + BM * LDS_PAD, tid);
    cp_commit();
    load_stage(A, B, K, bm, bn, BK, smem + STAGE_FLOATS,
               smem + STAGE_FLOATS + BM * LDS_PAD, tid);
    cp_commit();

    int stage = 0;
    for (int kt = 0; kt < kIters; kt++) {
        cp_wait1();
        __syncthreads();

        int nk = kt + 2;
        if (nk < kIters) {
            int ns = nk % 3;
            load_stage(A, B, K, bm, bn, nk * BK,
                       smem + ns * STAGE_FLOATS,
                       smem + ns * STAGE_FLOATS + BM * LDS_PAD, tid);
        }
        cp_commit();

        const float* As = smem + stage * STAGE_FLOATS;
        const float* Bs = As + BM * LDS_PAD;

        #pragma unroll
        for (int kk = 0; kk < BK; kk += 8) {
            wmma::fragment<wmma::matrix_a, 16, 16, 8, wmma::precision::tf32, wmma::row_major> af[4];
            #pragma unroll
            for (int i = 0; i < 4; i++) {
                wmma::load_matrix_sync(af[i], As + (wm + i * 16) * LDS_PAD + kk, LDS_PAD);
                #pragma unroll
                for (int e = 0; e < af[i].num_elements; e++)
                    af[i].x[e] = wmma::__float_to_tf32(af[i].x[e]);
            }
            #pragma unroll
            for (int j = 0; j < 4; j++) {
                wmma::fragment<wmma::matrix_b, 16, 16, 8, wmma::precision::tf32, wmma::col_major> bf;
                wmma::load_matrix_sync(bf, Bs + (wn + j * 16) * LDS_PAD + kk, LDS_PAD);
                #pragma unroll
                for (int e = 0; e < bf.num_elements; e++)
                    bf.x[e] = wmma::__float_to_tf32(bf.x[e]);
                #pragma unroll
                for (int i = 0; i < 4; i++)
                    wmma::mma_sync(acc[i][j], af[i], bf, acc[i][j]);
            }
        }

        stage = (stage + 1 == 3) ? 0 : stage + 1;
    }

    #pragma unroll
    for (int i = 0; i < 4; i++)
        #pragma unroll
        for (int j = 0; j < 4; j++)
            wmma::store_matrix_sync(C + (size_t)(bm + wm + i * 16) * N + (bn + wn + j * 16),
                                    acc[i][j], N, wmma::mem_row_major);
}

// ---------------------------------------------------------------------------
// Bias add + RoPE on q,k (pairs over full hidden dim); bias add on v.
// ---------------------------------------------------------------------------
__global__ void rope_bias_kernel(const float* __restrict__ bq,
                                 const float* __restrict__ bk,
                                 const float* __restrict__ bv, int M) {
    int idx = blockIdx.x * blockDim.x + threadIdx.x;
    if (idx >= M * HALF_D) return;
    int row = idx / HALF_D;
    int i   = idx - row * HALF_D;
    int pos = row & (SLEN - 1);

    float c = g_cos[pos * HALF_D + i];
    float s = g_sin[pos * HALF_D + i];

    size_t base = (size_t)row * HID + 2 * i;
    float b0, b1;

    float2 qv = *(float2*)&g_q[base];
    b0 = bq[2 * i]; b1 = bq[2 * i + 1];
    qv.x += b0; qv.y += b1;
    float2 qr = make_float2(c * qv.x - s * qv.y, s * qv.x + c * qv.y);
    *(float2*)&g_q[base] = qr;

    float2 kv = *(float2*)&g_k[base];
    b0 = bk[2 * i]; b1 = bk[2 * i + 1];
    kv.x += b0; kv.y += b1;
    float2 kr = make_float2(c * kv.x - s * kv.y, s * kv.x + c * kv.y);
    *(float2*)&g_k[base] = kr;

    float2 vv = *(float2*)&g_v[base];
    vv.x += bv[2 * i]; vv.y += bv[2 * i + 1];
    *(float2*)&g_v[base] = vv;
}

// ---------------------------------------------------------------------------
// Head-mixing attention: per position p, 16x16 logits over heads, softmax,
// weighted sum of v. One block (256 threads) per position.
// ---------------------------------------------------------------------------
__global__ __launch_bounds__(256)
void attention_kernel(int M) {
    __shared__ float qt[DH * NHEADS];   // [j][n]
    __shared__ float kt[DH * NHEADS];   // [j][m]
    __shared__ float vs[HID];           // [m*DH + j]
    __shared__ float w[NHEADS * NHEADS];

    int p = blockIdx.x;
    int t = threadIdx.x;
    const float* qrow = g_q + (size_t)p * HID;
    const float* krow = g_k + (size_t)p * HID;
    const float* vrow = g_v + (size_t)p * HID;

    for (int c = t; c < HID; c += 256) {
        int n = c / DH;
        int j = c - n * DH;
        qt[j * NHEADS + n] = qrow[c];
        kt[j * NHEADS + n] = krow[c];
        vs[c] = vrow[c];
    }
    __syncthreads();

    {
        int m = t >> 4;
        int n = t & 15;
        float acc = 0.0f;
        #pragma unroll 8
        for (int j = 0; j < DH; j++)
            acc += qt[j * NHEADS + n] * kt[j * NHEADS + m];
        w[n * NHEADS + m] = acc * (1.0f / 12.0f);   // 1/sqrt(144)
    }
    __syncthreads();

    if (t < NHEADS) {
        float mx = -1e30f;
        #pragma unroll
        for (int m = 0; m < NHEADS; m++) mx = fmaxf(mx, w[t * NHEADS + m]);
        float sum = 0.0f;
        #pragma unroll
        for (int m = 0; m < NHEADS; m++) {
            float e = expf(w[t * NHEADS + m] - mx);
            w[t * NHEADS + m] = e;
            sum += e;
        }
        float inv = 1.0f / sum;
        #pragma unroll
        for (int m = 0; m < NHEADS; m++) w[t * NHEADS + m] *= inv;
    }
    __syncthreads();

    float* arow = g_attn + (size_t)p * HID;
    for (int c = t; c < HID; c += 256) {
        int n = c / DH;
        int j = c - n * DH;
        float acc = 0.0f;
        #pragma unroll
        for (int m = 0; m < NHEADS; m++)
            acc += w[n * NHEADS + m] * vs[m * DH + j];
        arow[c] = acc;
    }
}

// ---------------------------------------------------------------------------
// y = x + o + bo; out = LayerNorm(y) * g + b. One block per row.
// ---------------------------------------------------------------------------
__device__ __forceinline__ float block_sum(float v, float* red) {
    #pragma unroll
    for (int o = 16; o > 0; o >>= 1) v += __shfl_xor_sync(0xFFFFFFFFu, v, o);
    int warp = threadIdx.x >> 5, lane = threadIdx.x & 31;
    if (lane == 0) red[warp] = v;
    __syncthreads();
    if (warp == 0) {
        float x = (lane < 8) ? red[lane] : 0.0f;
        #pragma unroll
        for (int o = 4; o > 0; o >>= 1) x += __shfl_xor_sync(0xFFFFFFFFu, x, o);
        if (lane == 0) red[0] = x;
    }
    __syncthreads();
    float r = red[0];
    __syncthreads();
    return r;
}

__global__ __launch_bounds__(256)
void ln_kernel(const float* __restrict__ x, const float* __restrict__ bo,
               const float* __restrict__ gamma, const float* __restrict__ beta,
               float* __restrict__ out) {
    __shared__ float ybuf[HID];
    __shared__ float red[8];

    int row = blockIdx.x;
    int t = threadIdx.x;
    const float* xr = x + (size_t)row * HID;
    const float* orow = g_o + (size_t)row * HID;

    float s = 0.0f;
    for (int c = t; c < HID; c += 256) {
        float y = xr[c] + orow[c] + bo[c];
        ybuf[c] = y;
        s += y;
    }
    float total = block_sum(s, red);
    float mu = total * (1.0f / (float)HID);

    float vsum = 0.0f;
    for (int c = t; c < HID; c += 256) {
        float dy = ybuf[c] - mu;
        vsum += dy * dy;
    }
    float vtot = block_sum(vsum, red);
    float var = vtot * (1.0f / (float)HID);
    float rstd = rsqrtf(var + 1e-5f);

    float* orow_out = out + (size_t)row * HID;
    for (int c = t; c < HID; c += 256) {
        orow_out[c] = (ybuf[c] - mu) * rstd * gamma[c] + beta[c];
    }
}

// ---------------------------------------------------------------------------
extern "C" void kernel_launch(void* const* d_in, const int* in_sizes, int n_in,
                              void* d_out, int out_size) {
    const float* x  = (const float*)d_in[0];
    const float* wq = (const float*)d_in[1];
    const float* bq = (const float*)d_in[2];
    const float* wk = (const float*)d_in[3];
    const float* bk = (const float*)d_in[4];
    const float* wv = (const float*)d_in[5];
    const float* bv = (const float*)d_in[6];
    const float* wo = (const float*)d_in[7];
    const float* bo = (const float*)d_in[8];
    const float* g  = (const float*)d_in[9];
    const float* bl = (const float*)d_in[10];
    float* out = (float*)d_out;

    int M = in_sizes[0] / HID;   // b*s = 8192

    float *q, *k, *v, *attn, *o;
    cudaGetSymbolAddress((void**)&q,    g_q);
    cudaGetSymbolAddress((void**)&k,    g_k);
    cudaGetSymbolAddress((void**)&v,    g_v);
    cudaGetSymbolAddress((void**)&attn, g_attn);
    cudaGetSymbolAddress((void**)&o,    g_o);

    static int smem_set = 0;
    if (!smem_set) {
        cudaFuncSetAttribute(gemm_tf32_kernel,
                             cudaFuncAttributeMaxDynamicSharedMemorySize,
                             GEMM_SMEM_BYTES);
        smem_set = 1;
    }

    build_omega_kernel<<<(HALF_D + 255) / 256, 256>>>();
    build_rope_kernel<<<(SLEN * HALF_D + 255) / 256, 256>>>();

    dim3 ggrid(HID / BN, M / BM);   // 9 x 64
    gemm_tf32_kernel<<<ggrid, 256, GEMM_SMEM_BYTES>>>(x, wq, q, M, HID, HID);
    gemm_tf32_kernel<<<ggrid, 256, GEMM_SMEM_BYTES>>>(x, wk, k, M, HID, HID);
    gemm_tf32_kernel<<<ggrid, 256, GEMM_SMEM_BYTES>>>(x, wv, v, M, HID, HID);

    rope_bias_kernel<<<(M * HALF_D + 255) / 256, 256>>>(bq, bk, bv, M);

    attention_kernel<<<M, 256>>>(M);

    gemm_tf32_kernel<<<ggrid, 256, GEMM_SMEM_BYTES>>>(attn, wo, o, M, HID, HID);

    ln_kernel<<<M, 256>>>(x, bo, g, bl, out);

    (void)n_in; (void)out_size;
}